// round 1
// baseline (speedup 1.0000x reference)
#include <cuda_runtime.h>
#include <math.h>

#define NN   99000
#define NH   64
#define NNZC 1584000
#define NPT  33000

// ---------------- scratch (device globals; no runtime allocation) ----------------
__device__ float g_hid[NN * NH];
__device__ float g_s0[NN * NH];
__device__ float g_s1[NN * NH];
__device__ float g_s2[NN * NH];
__device__ float g_s3[NN * NH];
__device__ float g_t0[NN * NH];
__device__ float g_t1[NN * NH];
__device__ float g_logits[NN * 2];

__device__ __forceinline__ float* state_ptr(int id) {
    switch (id) {
        case 0: return g_s0;
        case 1: return g_s1;
        case 2: return g_s2;
        default: return g_s3;
    }
}

__device__ __forceinline__ void red_add_v4(float* p, float4 v) {
    asm volatile("red.global.add.v4.f32 [%0], {%1,%2,%3,%4};"
                 :: "l"(p), "f"(v.x), "f"(v.y), "f"(v.z), "f"(v.w)
                 : "memory");
}

__device__ __forceinline__ float warp_sum(float v) {
    #pragma unroll
    for (int o = 16; o > 0; o >>= 1) v += __shfl_xor_sync(0xffffffffu, v, o);
    return v;
}

// ---------------- generic [rows,64] @ [64,64]^T + bias ----------------
// block: 256 threads handles 32 rows. Wt[k][j] = W[j][k] in shared.
__device__ __forceinline__ void gemm64_body(const float* __restrict__ X,
                                            const float* __restrict__ W,
                                            const float* __restrict__ bias,
                                            float* __restrict__ Y, int nrows) {
    __shared__ float Wt[64][68];
    __shared__ float Xs[32][68];
    __shared__ float bs[64];
    int t = threadIdx.x;
    for (int i = t; i < 4096; i += 256) {
        int j = i >> 6, k = i & 63;
        Wt[k][j] = W[i];
    }
    if (t < 64) bs[t] = bias[t];
    int row0 = blockIdx.x * 32;
    for (int i = t; i < 512; i += 256) {
        int r = i >> 4, q = i & 15;
        float4 v = make_float4(0.f, 0.f, 0.f, 0.f);
        if (row0 + r < nrows) v = *(const float4*)&X[(size_t)(row0 + r) * 64 + q * 4];
        *(float4*)&Xs[r][q * 4] = v;
    }
    __syncthreads();
    int nd = t >> 3;
    int cg = (t & 7) * 8;
    float acc[8];
    #pragma unroll
    for (int j = 0; j < 8; j++) acc[j] = bs[cg + j];
    #pragma unroll
    for (int k = 0; k < 64; k++) {
        float xv = Xs[nd][k];
        float4 w0 = *(const float4*)&Wt[k][cg];
        float4 w1 = *(const float4*)&Wt[k][cg + 4];
        acc[0] += xv * w0.x; acc[1] += xv * w0.y; acc[2] += xv * w0.z; acc[3] += xv * w0.w;
        acc[4] += xv * w1.x; acc[5] += xv * w1.y; acc[6] += xv * w1.z; acc[7] += xv * w1.w;
    }
    int r = row0 + nd;
    if (r < nrows) {
        *(float4*)&Y[(size_t)r * 64 + cg]     = make_float4(acc[0], acc[1], acc[2], acc[3]);
        *(float4*)&Y[(size_t)r * 64 + cg + 4] = make_float4(acc[4], acc[5], acc[6], acc[7]);
    }
}

// type-wise input projection: 3 GEMMs selected by blockIdx.y
__global__ void proj_kernel(const float* __restrict__ f0, const float* __restrict__ f1,
                            const float* __restrict__ f2, const float* __restrict__ wsW,
                            const float* __restrict__ wsb) {
    int type = blockIdx.y;
    const float* X = (type == 0) ? f0 : (type == 1) ? f1 : f2;
    gemm64_body(X, wsW + (size_t)type * 4096, wsb + type * 64,
                g_hid + (size_t)type * NPT * 64, NPT);
}

// cell affine: x = hid @ W[m]^T + b[m] -> g_s0
__global__ void aff_kernel(const float* __restrict__ cW, const float* __restrict__ cb, int m) {
    gemm64_body(g_hid, cW + (size_t)m * 4096, cb + m * 64, g_s0, NN);
}

__global__ void zero_kernel(int dst_id) {
    float4* p = (float4*)state_ptr(dst_id);
    int i = blockIdx.x * 256 + threadIdx.x;
    if (i < NN * NH / 4) p[i] = make_float4(0.f, 0.f, 0.f, 0.f);
}

// COO spmm scatter: 16 threads per nnz, float4 per thread, red.v4 atomic.
// up to 3 (source-state, adjacency-index-location) pairs per launch via blockIdx.y
__global__ void spmm_kernel(const int* __restrict__ rows, const int* __restrict__ cols,
                            const float* __restrict__ vals,
                            int src0, const int* a0,
                            int src1, const int* a1,
                            int src2, const int* a2, int dst_id) {
    int pair = blockIdx.y;
    int src = (pair == 0) ? src0 : (pair == 1) ? src1 : src2;
    const int* ap = (pair == 0) ? a0 : (pair == 1) ? a1 : a2;
    int aidx = *ap;                       // which of the 6 adjacency slices
    size_t base = (size_t)aidx * NNZC;

    int tid = blockIdx.x * 256 + threadIdx.x;
    int e = tid >> 4;
    if (e >= NNZC) return;
    int q = tid & 15;

    int r = rows[base + e];
    int c = cols[base + e];
    float v = vals[base + e];

    const float* S = state_ptr(src);
    float* D = state_ptr(dst_id);
    float4 xv = *(const float4*)&S[(size_t)c * 64 + q * 4];
    red_add_v4(&D[(size_t)r * 64 + q * 4],
               make_float4(v * xv.x, v * xv.y, v * xv.z, v * xv.w));
}

// layernorm + exact gelu + attention logit. 8 warps/block, one warp per node.
__global__ void post_kernel(const float* __restrict__ gvec, const float* __restrict__ bvec,
                            const float* __restrict__ A1, const float* __restrict__ b1,
                            const float* __restrict__ a2, const float* __restrict__ b2,
                            int meta) {
    __shared__ float A1s[64][68];
    __shared__ float hs[8][68];
    __shared__ float b1s[64];
    __shared__ float a2s[64];
    int t = threadIdx.x;
    for (int i = t; i < 4096; i += 256) {
        int a = i >> 6, k = i & 63;
        A1s[a][k] = A1[i];
    }
    if (t < 64) { b1s[t] = b1[t]; a2s[t] = a2[t]; }
    __syncthreads();

    int w = t >> 5;
    int lane = t & 31;
    int node = blockIdx.x * 8 + w;
    if (node >= NN) return;

    float* T = meta ? g_t1 : g_t0;
    const float* S = g_s3;

    float h0 = S[(size_t)node * 64 + lane];
    float h1 = S[(size_t)node * 64 + lane + 32];
    float mu = warp_sum(h0 + h1) * (1.0f / 64.0f);
    float d0 = h0 - mu, d1 = h1 - mu;
    float var = warp_sum(d0 * d0 + d1 * d1) * (1.0f / 64.0f);
    float rstd = rsqrtf(var + 1e-5f);
    float n0 = d0 * rstd * gvec[lane] + bvec[lane];
    float n1 = d1 * rstd * gvec[lane + 32] + bvec[lane + 32];
    // exact gelu
    float ge0 = 0.5f * n0 * (1.0f + erff(n0 * 0.70710678118654752f));
    float ge1 = 0.5f * n1 * (1.0f + erff(n1 * 0.70710678118654752f));
    T[(size_t)node * 64 + lane] = ge0;
    T[(size_t)node * 64 + lane + 32] = ge1;
    hs[w][lane] = ge0;
    hs[w][lane + 32] = ge1;
    __syncwarp();

    // logit = tanh(A1 h + b1) . a2 + b2
    float part = 0.f;
    #pragma unroll
    for (int half = 0; half < 2; half++) {
        int a = lane + half * 32;
        float acc = b1s[a];
        #pragma unroll
        for (int k4 = 0; k4 < 16; k4++) {
            float4 wv = *(const float4*)&A1s[a][k4 * 4];
            float4 hv = *(const float4*)&hs[w][k4 * 4];
            acc += wv.x * hv.x + wv.y * hv.y + wv.z * hv.z + wv.w * hv.w;
        }
        part += tanhf(acc) * a2s[a];
    }
    part = warp_sum(part);
    if (lane == 0) g_logits[node * 2 + meta] = part + b2[0];
}

// 2-way softmax over metas + weighted sum -> out
__global__ void mix_kernel(float* __restrict__ out) {
    int idx = blockIdx.x * 256 + threadIdx.x;
    if (idx >= NN * 16) return;
    int node = idx >> 4, q = idx & 15;
    float l0 = g_logits[node * 2 + 0];
    float l1 = g_logits[node * 2 + 1];
    float mx = fmaxf(l0, l1);
    float e0 = expf(l0 - mx), e1 = expf(l1 - mx);
    float inv = 1.0f / (e0 + e1);
    float w0 = e0 * inv, w1 = e1 * inv;
    float4 a = *(const float4*)&g_t0[(size_t)node * 64 + q * 4];
    float4 b = *(const float4*)&g_t1[(size_t)node * 64 + q * 4];
    *(float4*)&out[(size_t)node * 64 + q * 4] =
        make_float4(w0 * a.x + w1 * b.x, w0 * a.y + w1 * b.y,
                    w0 * a.z + w1 * b.z, w0 * a.w + w1 * b.w);
}

extern "C" void kernel_launch(void* const* d_in, const int* in_sizes, int n_in,
                              void* d_out, int out_size) {
    const float* feats0      = (const float*)d_in[0];
    const float* feats1      = (const float*)d_in[1];
    const float* feats2      = (const float*)d_in[2];
    const float* ws_W        = (const float*)d_in[3];
    const float* ws_b        = (const float*)d_in[4];
    const float* adj_vals    = (const float*)d_in[5];
    const float* cell_aff_W  = (const float*)d_in[6];
    const float* cell_aff_b  = (const float*)d_in[7];
    const float* cell_norm_g = (const float*)d_in[8];
    const float* cell_norm_b = (const float*)d_in[9];
    const float* attn1_W     = (const float*)d_in[10];
    const float* attn1_b     = (const float*)d_in[11];
    const float* attn2_W     = (const float*)d_in[12];
    const float* attn2_b     = (const float*)d_in[13];
    // d_in[14] = node_types (types are contiguous blocks; unused)
    const int* adj_rows      = (const int*)d_in[15];
    const int* adj_cols      = (const int*)d_in[16];
    const int* idxes_seq     = (const int*)d_in[17];   // [2,3]
    const int* idxes_res     = (const int*)d_in[18];   // [2,3]
    float* out = (float*)d_out;

    const int GEMM_BLOCKS_ALL  = (NN + 31) / 32;       // 3094
    const int GEMM_BLOCKS_TYPE = (NPT + 31) / 32;      // 1032
    const int SPMM_BLOCKS = (NNZC * 16) / 256;         // 99000
    const int ZERO_BLOCKS = (NN * NH / 4 + 255) / 256; // 6188
    const int POST_BLOCKS = (NN + 7) / 8;              // 12375
    const int MIX_BLOCKS  = (NN * 16 + 255) / 256;     // 6188

    // 1) type-wise projection -> g_hid
    proj_kernel<<<dim3(GEMM_BLOCKS_TYPE, 3), 256>>>(feats0, feats1, feats2, ws_W, ws_b);

    for (int m = 0; m < 2; m++) {
        const int* seq = idxes_seq + m * 3;
        const int* res = idxes_res + m * 3;

        // states[0] = hid @ cell_aff_W[m]^T + b
        aff_kernel<<<GEMM_BLOCKS_ALL, 256>>>(cell_aff_W, cell_aff_b, m);

        // states[1] = spmm(seq0, s0)
        zero_kernel<<<ZERO_BLOCKS, 256>>>(1);
        spmm_kernel<<<dim3(SPMM_BLOCKS, 1), 256>>>(adj_rows, adj_cols, adj_vals,
                                                   0, seq + 0, 0, seq + 0, 0, seq + 0, 1);
        // states[2] = spmm(seq1, s1) + spmm(res0, s0)
        zero_kernel<<<ZERO_BLOCKS, 256>>>(2);
        spmm_kernel<<<dim3(SPMM_BLOCKS, 2), 256>>>(adj_rows, adj_cols, adj_vals,
                                                   1, seq + 1, 0, res + 0, 0, res + 0, 2);
        // states[3] = spmm(seq2, s2) + spmm(res1, s0) + spmm(res2, s1)
        zero_kernel<<<ZERO_BLOCKS, 256>>>(3);
        spmm_kernel<<<dim3(SPMM_BLOCKS, 3), 256>>>(adj_rows, adj_cols, adj_vals,
                                                   2, seq + 2, 0, res + 1, 1, res + 2, 3);

        // layernorm + gelu + attention logit
        post_kernel<<<POST_BLOCKS, 256>>>(cell_norm_g + m * 64, cell_norm_b + m * 64,
                                          attn1_W, attn1_b, attn2_W, attn2_b, m);
    }

    // softmax over 2 metas + weighted sum
    mix_kernel<<<MIX_BLOCKS, 256>>>(out);
}

// round 2
// speedup vs baseline: 1.2617x; 1.2617x over previous
#include <cuda_runtime.h>
#include <math.h>

#define NN   99000
#define NH   64
#define NNZC 1584000
#define NADJ 6
#define NPT  33000

// ---------------- scratch (device globals; no runtime allocation) ----------------
__device__ float g_hid[NN * NH];
__device__ float g_s0[NN * NH];
__device__ float g_s1[NN * NH];
__device__ float g_s2[NN * NH];
__device__ float g_s3[NN * NH];
__device__ float g_t0[NN * NH];
__device__ float g_t1[NN * NH];
__device__ float g_logits[NN * 2];

// CSR scratch
__device__ int  g_cursor[NADJ * NN];          // histogram, then cursor
__device__ int  g_rowptr[NADJ * (NN + 1)];
__device__ int2 g_pack[(size_t)NADJ * NNZC];  // (col, val bits) sorted by row

__device__ __forceinline__ float* state_ptr(int id) {
    switch (id) {
        case 0: return g_s0;
        case 1: return g_s1;
        case 2: return g_s2;
        default: return g_s3;
    }
}

__device__ __forceinline__ float warp_sum(float v) {
    #pragma unroll
    for (int o = 16; o > 0; o >>= 1) v += __shfl_xor_sync(0xffffffffu, v, o);
    return v;
}

// ---------------- CSR build ----------------
__global__ void zero_counts_kernel() {
    int i = blockIdx.x * 256 + threadIdx.x;
    if (i < NADJ * NN) g_cursor[i] = 0;
}

__global__ void hist_kernel(const int* __restrict__ rows) {
    int i = blockIdx.x * 256 + threadIdx.x;
    if (i >= NADJ * NNZC) return;
    int a = i / NNZC;
    atomicAdd(&g_cursor[a * NN + rows[i]], 1);
}

// one block per adjacency: sequential chunked exclusive scan (1024 thr)
__global__ void scan_kernel() {
    __shared__ int sh[1024];
    int a = blockIdx.x, t = threadIdx.x;
    int* cnt = g_cursor + a * NN;
    int* rp  = g_rowptr + a * (NN + 1);
    int carry = 0;
    for (int base = 0; base < NN; base += 1024) {
        int idx = base + t;
        int v = (idx < NN) ? cnt[idx] : 0;
        sh[t] = v;
        __syncthreads();
        #pragma unroll
        for (int off = 1; off < 1024; off <<= 1) {
            int add = (t >= off) ? sh[t - off] : 0;
            __syncthreads();
            sh[t] += add;
            __syncthreads();
        }
        int incl = sh[t];
        int total = sh[1023];
        if (idx < NN) {
            int excl = carry + incl - v;
            rp[idx]  = excl;
            cnt[idx] = excl;   // cursor for scatter
        }
        carry += total;
        __syncthreads();
    }
    if (t == 0) rp[NN] = carry;
}

__global__ void scatter_kernel(const int* __restrict__ rows, const int* __restrict__ cols,
                               const float* __restrict__ vals) {
    int i = blockIdx.x * 256 + threadIdx.x;
    if (i >= NADJ * NNZC) return;
    int a = i / NNZC;
    int r = rows[i];
    int pos = atomicAdd(&g_cursor[a * NN + r], 1);
    g_pack[(size_t)a * NNZC + pos] = make_int2(cols[i], __float_as_int(vals[i]));
}

// ---------------- fused gather SpMM: out[row] = sum_pairs sum_nnz v * S[c] ----------------
// one warp per row; each lane owns 2 of the 64 columns (float2).
__global__ void spmm_gather_kernel(int npairs,
                                   int src0, const int* a0,
                                   int src1, const int* a1,
                                   int src2, const int* a2, int dst_id) {
    int gid = blockIdx.x * 256 + threadIdx.x;
    int row = gid >> 5;
    if (row >= NN) return;
    int lane2 = (threadIdx.x & 31) * 2;

    float ax = 0.f, ay = 0.f;
    #pragma unroll 3
    for (int p = 0; p < 3; p++) {
        if (p >= npairs) break;
        int src = (p == 0) ? src0 : (p == 1) ? src1 : src2;
        const int* ap = (p == 0) ? a0 : (p == 1) ? a1 : a2;
        int aidx = *ap;
        const float* __restrict__ S = state_ptr(src);
        const int* rp = g_rowptr + aidx * (NN + 1);
        int j   = rp[row];
        int end = rp[row + 1];
        const int2* __restrict__ pk = g_pack + (size_t)aidx * NNZC;

        for (; j + 4 <= end; j += 4) {
            int2 e0 = pk[j], e1 = pk[j + 1], e2 = pk[j + 2], e3 = pk[j + 3];
            float2 x0 = *(const float2*)&S[(size_t)e0.x * 64 + lane2];
            float2 x1 = *(const float2*)&S[(size_t)e1.x * 64 + lane2];
            float2 x2 = *(const float2*)&S[(size_t)e2.x * 64 + lane2];
            float2 x3 = *(const float2*)&S[(size_t)e3.x * 64 + lane2];
            float v0 = __int_as_float(e0.y), v1 = __int_as_float(e1.y);
            float v2 = __int_as_float(e2.y), v3 = __int_as_float(e3.y);
            ax += v0 * x0.x; ay += v0 * x0.y;
            ax += v1 * x1.x; ay += v1 * x1.y;
            ax += v2 * x2.x; ay += v2 * x2.y;
            ax += v3 * x3.x; ay += v3 * x3.y;
        }
        for (; j < end; j++) {
            int2 e = pk[j];
            float v = __int_as_float(e.y);
            float2 xv = *(const float2*)&S[(size_t)e.x * 64 + lane2];
            ax += v * xv.x; ay += v * xv.y;
        }
    }
    float* D = state_ptr(dst_id);
    *(float2*)&D[(size_t)row * 64 + lane2] = make_float2(ax, ay);
}

// ---------------- generic [rows,64] @ [64,64]^T + bias ----------------
__device__ __forceinline__ void gemm64_body(const float* __restrict__ X,
                                            const float* __restrict__ W,
                                            const float* __restrict__ bias,
                                            float* __restrict__ Y, int nrows) {
    __shared__ float Wt[64][68];
    __shared__ float Xs[32][68];
    __shared__ float bs[64];
    int t = threadIdx.x;
    for (int i = t; i < 4096; i += 256) {
        int j = i >> 6, k = i & 63;
        Wt[k][j] = W[i];
    }
    if (t < 64) bs[t] = bias[t];
    int row0 = blockIdx.x * 32;
    for (int i = t; i < 512; i += 256) {
        int r = i >> 4, q = i & 15;
        float4 v = make_float4(0.f, 0.f, 0.f, 0.f);
        if (row0 + r < nrows) v = *(const float4*)&X[(size_t)(row0 + r) * 64 + q * 4];
        *(float4*)&Xs[r][q * 4] = v;
    }
    __syncthreads();
    int nd = t >> 3;
    int cg = (t & 7) * 8;
    float acc[8];
    #pragma unroll
    for (int j = 0; j < 8; j++) acc[j] = bs[cg + j];
    #pragma unroll
    for (int k = 0; k < 64; k++) {
        float xv = Xs[nd][k];
        float4 w0 = *(const float4*)&Wt[k][cg];
        float4 w1 = *(const float4*)&Wt[k][cg + 4];
        acc[0] += xv * w0.x; acc[1] += xv * w0.y; acc[2] += xv * w0.z; acc[3] += xv * w0.w;
        acc[4] += xv * w1.x; acc[5] += xv * w1.y; acc[6] += xv * w1.z; acc[7] += xv * w1.w;
    }
    int r = row0 + nd;
    if (r < nrows) {
        *(float4*)&Y[(size_t)r * 64 + cg]     = make_float4(acc[0], acc[1], acc[2], acc[3]);
        *(float4*)&Y[(size_t)r * 64 + cg + 4] = make_float4(acc[4], acc[5], acc[6], acc[7]);
    }
}

__global__ void proj_kernel(const float* __restrict__ f0, const float* __restrict__ f1,
                            const float* __restrict__ f2, const float* __restrict__ wsW,
                            const float* __restrict__ wsb) {
    int type = blockIdx.y;
    const float* X = (type == 0) ? f0 : (type == 1) ? f1 : f2;
    gemm64_body(X, wsW + (size_t)type * 4096, wsb + type * 64,
                g_hid + (size_t)type * NPT * 64, NPT);
}

__global__ void aff_kernel(const float* __restrict__ cW, const float* __restrict__ cb, int m) {
    gemm64_body(g_hid, cW + (size_t)m * 4096, cb + m * 64, g_s0, NN);
}

// layernorm + exact gelu + attention logit. 8 warps/block, one warp per node.
__global__ void post_kernel(const float* __restrict__ gvec, const float* __restrict__ bvec,
                            const float* __restrict__ A1, const float* __restrict__ b1,
                            const float* __restrict__ a2, const float* __restrict__ b2,
                            int meta) {
    __shared__ float A1s[64][68];
    __shared__ float hs[8][68];
    __shared__ float b1s[64];
    __shared__ float a2s[64];
    int t = threadIdx.x;
    for (int i = t; i < 4096; i += 256) {
        int a = i >> 6, k = i & 63;
        A1s[a][k] = A1[i];
    }
    if (t < 64) { b1s[t] = b1[t]; a2s[t] = a2[t]; }
    __syncthreads();

    int w = t >> 5;
    int lane = t & 31;
    int node = blockIdx.x * 8 + w;
    if (node >= NN) return;

    float* T = meta ? g_t1 : g_t0;
    const float* S = g_s3;

    float h0 = S[(size_t)node * 64 + lane];
    float h1 = S[(size_t)node * 64 + lane + 32];
    float mu = warp_sum(h0 + h1) * (1.0f / 64.0f);
    float d0 = h0 - mu, d1 = h1 - mu;
    float var = warp_sum(d0 * d0 + d1 * d1) * (1.0f / 64.0f);
    float rstd = rsqrtf(var + 1e-5f);
    float n0 = d0 * rstd * gvec[lane] + bvec[lane];
    float n1 = d1 * rstd * gvec[lane + 32] + bvec[lane + 32];
    float ge0 = 0.5f * n0 * (1.0f + erff(n0 * 0.70710678118654752f));
    float ge1 = 0.5f * n1 * (1.0f + erff(n1 * 0.70710678118654752f));
    T[(size_t)node * 64 + lane] = ge0;
    T[(size_t)node * 64 + lane + 32] = ge1;
    hs[w][lane] = ge0;
    hs[w][lane + 32] = ge1;
    __syncwarp();

    float part = 0.f;
    #pragma unroll
    for (int half = 0; half < 2; half++) {
        int a = lane + half * 32;
        float acc = b1s[a];
        #pragma unroll
        for (int k4 = 0; k4 < 16; k4++) {
            float4 wv = *(const float4*)&A1s[a][k4 * 4];
            float4 hv = *(const float4*)&hs[w][k4 * 4];
            acc += wv.x * hv.x + wv.y * hv.y + wv.z * hv.z + wv.w * hv.w;
        }
        part += tanhf(acc) * a2s[a];
    }
    part = warp_sum(part);
    if (lane == 0) g_logits[node * 2 + meta] = part + b2[0];
}

// 2-way softmax over metas + weighted sum -> out
__global__ void mix_kernel(float* __restrict__ out) {
    int idx = blockIdx.x * 256 + threadIdx.x;
    if (idx >= NN * 16) return;
    int node = idx >> 4, q = idx & 15;
    float l0 = g_logits[node * 2 + 0];
    float l1 = g_logits[node * 2 + 1];
    float mx = fmaxf(l0, l1);
    float e0 = expf(l0 - mx), e1 = expf(l1 - mx);
    float inv = 1.0f / (e0 + e1);
    float w0 = e0 * inv, w1 = e1 * inv;
    float4 a = *(const float4*)&g_t0[(size_t)node * 64 + q * 4];
    float4 b = *(const float4*)&g_t1[(size_t)node * 64 + q * 4];
    *(float4*)&out[(size_t)node * 64 + q * 4] =
        make_float4(w0 * a.x + w1 * b.x, w0 * a.y + w1 * b.y,
                    w0 * a.z + w1 * b.z, w0 * a.w + w1 * b.w);
}

extern "C" void kernel_launch(void* const* d_in, const int* in_sizes, int n_in,
                              void* d_out, int out_size) {
    const float* feats0      = (const float*)d_in[0];
    const float* feats1      = (const float*)d_in[1];
    const float* feats2      = (const float*)d_in[2];
    const float* ws_W        = (const float*)d_in[3];
    const float* ws_b        = (const float*)d_in[4];
    const float* adj_vals    = (const float*)d_in[5];
    const float* cell_aff_W  = (const float*)d_in[6];
    const float* cell_aff_b  = (const float*)d_in[7];
    const float* cell_norm_g = (const float*)d_in[8];
    const float* cell_norm_b = (const float*)d_in[9];
    const float* attn1_W     = (const float*)d_in[10];
    const float* attn1_b     = (const float*)d_in[11];
    const float* attn2_W     = (const float*)d_in[12];
    const float* attn2_b     = (const float*)d_in[13];
    // d_in[14] = node_types (contiguous blocks; unused)
    const int* adj_rows      = (const int*)d_in[15];
    const int* adj_cols      = (const int*)d_in[16];
    const int* idxes_seq     = (const int*)d_in[17];   // [2,3]
    const int* idxes_res     = (const int*)d_in[18];   // [2,3]
    float* out = (float*)d_out;

    const int GEMM_BLOCKS_ALL  = (NN + 31) / 32;
    const int GEMM_BLOCKS_TYPE = (NPT + 31) / 32;
    const int EDGE_BLOCKS  = (NADJ * NNZC + 255) / 256;
    const int CNT_BLOCKS   = (NADJ * NN + 255) / 256;
    const int GATH_BLOCKS  = (NN * 32 + 255) / 256;    // warp per row
    const int POST_BLOCKS  = (NN + 7) / 8;
    const int MIX_BLOCKS   = (NN * 16 + 255) / 256;

    // ---- CSR build (once per launch; reused by all 12 SpMM passes) ----
    zero_counts_kernel<<<CNT_BLOCKS, 256>>>();
    hist_kernel<<<EDGE_BLOCKS, 256>>>(adj_rows);
    scan_kernel<<<NADJ, 1024>>>();
    scatter_kernel<<<EDGE_BLOCKS, 256>>>(adj_rows, adj_cols, adj_vals);

    // ---- type-wise projection -> g_hid ----
    proj_kernel<<<dim3(GEMM_BLOCKS_TYPE, 3), 256>>>(feats0, feats1, feats2, ws_W, ws_b);

    for (int m = 0; m < 2; m++) {
        const int* seq = idxes_seq + m * 3;
        const int* res = idxes_res + m * 3;

        // states[0] = hid @ cell_aff_W[m]^T + b
        aff_kernel<<<GEMM_BLOCKS_ALL, 256>>>(cell_aff_W, cell_aff_b, m);

        // states[1] = spmm(seq0, s0)
        spmm_gather_kernel<<<GATH_BLOCKS, 256>>>(1, 0, seq + 0, 0, seq + 0, 0, seq + 0, 1);
        // states[2] = spmm(seq1, s1) + spmm(res0, s0)
        spmm_gather_kernel<<<GATH_BLOCKS, 256>>>(2, 1, seq + 1, 0, res + 0, 0, res + 0, 2);
        // states[3] = spmm(seq2, s2) + spmm(res1, s0) + spmm(res2, s1)
        spmm_gather_kernel<<<GATH_BLOCKS, 256>>>(3, 2, seq + 2, 0, res + 1, 1, res + 2, 3);

        // layernorm + gelu + attention logit
        post_kernel<<<POST_BLOCKS, 256>>>(cell_norm_g + m * 64, cell_norm_b + m * 64,
                                          attn1_W, attn1_b, attn2_W, attn2_b, m);
    }

    mix_kernel<<<MIX_BLOCKS, 256>>>(out);
}

// round 3
// speedup vs baseline: 1.5698x; 1.2442x over previous
#include <cuda_runtime.h>
#include <math.h>

#define NN   99000
#define NH   64
#define NNZC 1584000
#define NADJ 6
#define NPT  33000
#define NT   97          // scan tiles per adjacency: ceil(99000/1024)

// ---------------- scratch (device globals; no runtime allocation) ----------------
__device__ float g_hid[NN * NH];
__device__ float g_s0[NN * NH];
__device__ float g_s1[NN * NH];
__device__ float g_s2[NN * NH];
__device__ float g_s3[NN * NH];
__device__ float g_t0[NN * NH];
__device__ float g_t1[NN * NH];
__device__ float g_logits[NN * 2];

// CSR scratch
__device__ int  g_cursor[NADJ * NN];          // histogram, then cursor
__device__ int  g_rowptr[NADJ * (NN + 1)];
__device__ int  g_tilesum[NADJ * NT];
__device__ int  g_tileoff[NADJ * NT];
__device__ int2 g_pack[(size_t)NADJ * NNZC];  // (col, val bits) sorted by row

__device__ __forceinline__ float* state_ptr(int id) {
    switch (id) {
        case 0: return g_s0;
        case 1: return g_s1;
        case 2: return g_s2;
        default: return g_s3;
    }
}

__device__ __forceinline__ float warp_sum(float v) {
    #pragma unroll
    for (int o = 16; o > 0; o >>= 1) v += __shfl_xor_sync(0xffffffffu, v, o);
    return v;
}

// ---------------- CSR build ----------------
__global__ void zero_counts_kernel() {
    int i = blockIdx.x * 256 + threadIdx.x;
    if (i < NADJ * NN) g_cursor[i] = 0;
}

// 4 edges per thread (int4 loads)
__global__ void hist_kernel(const int* __restrict__ rows) {
    int i = blockIdx.x * 256 + threadIdx.x;
    if (i >= NADJ * NNZC / 4) return;
    int a = (i * 4) / NNZC;
    int4 r = *(const int4*)&rows[i * 4];
    int* cnt = g_cursor + a * NN;
    atomicAdd(&cnt[r.x], 1);
    atomicAdd(&cnt[r.y], 1);
    atomicAdd(&cnt[r.z], 1);
    atomicAdd(&cnt[r.w], 1);
}

// phase A: per-tile local exclusive scan (1024 threads), tile totals out
__global__ void scanA_kernel() {
    __shared__ int sh[32];
    int a = blockIdx.y, tile = blockIdx.x;
    int idx = tile * 1024 + threadIdx.x;
    int lane = threadIdx.x & 31, wid = threadIdx.x >> 5;
    int v = (idx < NN) ? g_cursor[a * NN + idx] : 0;
    int s = v;
    #pragma unroll
    for (int o = 1; o < 32; o <<= 1) {
        int n = __shfl_up_sync(0xffffffffu, s, o);
        if (lane >= o) s += n;
    }
    if (lane == 31) sh[wid] = s;
    __syncthreads();
    if (wid == 0) {
        int w = sh[lane];
        #pragma unroll
        for (int o = 1; o < 32; o <<= 1) {
            int n = __shfl_up_sync(0xffffffffu, w, o);
            if (lane >= o) w += n;
        }
        sh[lane] = w;
    }
    __syncthreads();
    int incl = s + ((wid > 0) ? sh[wid - 1] : 0);
    if (idx < NN) g_rowptr[a * (NN + 1) + idx] = incl - v;  // local exclusive
    if (threadIdx.x == 1023) g_tilesum[a * NT + tile] = incl;
}

// phase B: scan tile sums per adjacency (6 blocks, 128 threads; NT=97 < 128)
__global__ void scanB_kernel() {
    __shared__ int sh[4];
    int a = blockIdx.x, t = threadIdx.x;
    int lane = t & 31, wid = t >> 5;
    int orig = (t < NT) ? g_tilesum[a * NT + t] : 0;
    int s = orig;
    #pragma unroll
    for (int o = 1; o < 32; o <<= 1) {
        int n = __shfl_up_sync(0xffffffffu, s, o);
        if (lane >= o) s += n;
    }
    if (lane == 31) sh[wid] = s;
    __syncthreads();
    int add = 0;
    for (int w = 0; w < wid; w++) add += sh[w];
    int incl = s + add;
    if (t < NT) g_tileoff[a * NT + t] = incl - orig;  // exclusive tile offset
    if (t == NT - 1) g_rowptr[a * (NN + 1) + NN] = incl;  // grand total
}

// phase C: add tile offsets; produce final rowptr and cursor copy
__global__ void scanC_kernel() {
    int a = blockIdx.y;
    int idx = blockIdx.x * 1024 + threadIdx.x;
    if (idx >= NN) return;
    int off = g_tileoff[a * NT + blockIdx.x];
    int e = g_rowptr[a * (NN + 1) + idx] + off;
    g_rowptr[a * (NN + 1) + idx] = e;
    g_cursor[a * NN + idx] = e;
}

// 4 edges per thread
__global__ void scatter_kernel(const int* __restrict__ rows, const int* __restrict__ cols,
                               const float* __restrict__ vals) {
    int i = blockIdx.x * 256 + threadIdx.x;
    if (i >= NADJ * NNZC / 4) return;
    int a = (i * 4) / NNZC;
    int4 r = *(const int4*)&rows[i * 4];
    int4 c = *(const int4*)&cols[i * 4];
    float4 v = *(const float4*)&vals[i * 4];
    int* cur = g_cursor + a * NN;
    int2* pk = (int2*)(g_pack + (size_t)a * NNZC);
    int p0 = atomicAdd(&cur[r.x], 1);
    int p1 = atomicAdd(&cur[r.y], 1);
    int p2 = atomicAdd(&cur[r.z], 1);
    int p3 = atomicAdd(&cur[r.w], 1);
    pk[p0] = make_int2(c.x, __float_as_int(v.x));
    pk[p1] = make_int2(c.y, __float_as_int(v.y));
    pk[p2] = make_int2(c.z, __float_as_int(v.z));
    pk[p3] = make_int2(c.w, __float_as_int(v.w));
}

// ---------------- fused gather SpMM ----------------
// one warp per row; each lane owns 2 of the 64 columns. 8-edge unrolled batches.
__global__ void spmm_gather_kernel(int npairs,
                                   int src0, const int* a0,
                                   int src1, const int* a1,
                                   int src2, const int* a2, int dst_id) {
    int gid = blockIdx.x * 256 + threadIdx.x;
    int row = gid >> 5;
    if (row >= NN) return;
    int lane2 = (threadIdx.x & 31) * 2;

    float ax = 0.f, ay = 0.f;
    #pragma unroll 3
    for (int p = 0; p < 3; p++) {
        if (p >= npairs) break;
        int src = (p == 0) ? src0 : (p == 1) ? src1 : src2;
        const int* ap = (p == 0) ? a0 : (p == 1) ? a1 : a2;
        int aidx = *ap;
        const float* __restrict__ S = state_ptr(src);
        const int* rp = g_rowptr + aidx * (NN + 1);
        int j   = rp[row];
        int end = rp[row + 1];
        const int2* __restrict__ pk = g_pack + (size_t)aidx * NNZC;

        for (; j + 8 <= end; j += 8) {
            int2 e0 = pk[j],     e1 = pk[j + 1], e2 = pk[j + 2], e3 = pk[j + 3];
            int2 e4 = pk[j + 4], e5 = pk[j + 5], e6 = pk[j + 6], e7 = pk[j + 7];
            float2 x0 = *(const float2*)&S[(size_t)e0.x * 64 + lane2];
            float2 x1 = *(const float2*)&S[(size_t)e1.x * 64 + lane2];
            float2 x2 = *(const float2*)&S[(size_t)e2.x * 64 + lane2];
            float2 x3 = *(const float2*)&S[(size_t)e3.x * 64 + lane2];
            float2 x4 = *(const float2*)&S[(size_t)e4.x * 64 + lane2];
            float2 x5 = *(const float2*)&S[(size_t)e5.x * 64 + lane2];
            float2 x6 = *(const float2*)&S[(size_t)e6.x * 64 + lane2];
            float2 x7 = *(const float2*)&S[(size_t)e7.x * 64 + lane2];
            ax += __int_as_float(e0.y) * x0.x; ay += __int_as_float(e0.y) * x0.y;
            ax += __int_as_float(e1.y) * x1.x; ay += __int_as_float(e1.y) * x1.y;
            ax += __int_as_float(e2.y) * x2.x; ay += __int_as_float(e2.y) * x2.y;
            ax += __int_as_float(e3.y) * x3.x; ay += __int_as_float(e3.y) * x3.y;
            ax += __int_as_float(e4.y) * x4.x; ay += __int_as_float(e4.y) * x4.y;
            ax += __int_as_float(e5.y) * x5.x; ay += __int_as_float(e5.y) * x5.y;
            ax += __int_as_float(e6.y) * x6.x; ay += __int_as_float(e6.y) * x6.y;
            ax += __int_as_float(e7.y) * x7.x; ay += __int_as_float(e7.y) * x7.y;
        }
        for (; j + 4 <= end; j += 4) {
            int2 e0 = pk[j], e1 = pk[j + 1], e2 = pk[j + 2], e3 = pk[j + 3];
            float2 x0 = *(const float2*)&S[(size_t)e0.x * 64 + lane2];
            float2 x1 = *(const float2*)&S[(size_t)e1.x * 64 + lane2];
            float2 x2 = *(const float2*)&S[(size_t)e2.x * 64 + lane2];
            float2 x3 = *(const float2*)&S[(size_t)e3.x * 64 + lane2];
            ax += __int_as_float(e0.y) * x0.x; ay += __int_as_float(e0.y) * x0.y;
            ax += __int_as_float(e1.y) * x1.x; ay += __int_as_float(e1.y) * x1.y;
            ax += __int_as_float(e2.y) * x2.x; ay += __int_as_float(e2.y) * x2.y;
            ax += __int_as_float(e3.y) * x3.x; ay += __int_as_float(e3.y) * x3.y;
        }
        for (; j < end; j++) {
            int2 e = pk[j];
            float v = __int_as_float(e.y);
            float2 xv = *(const float2*)&S[(size_t)e.x * 64 + lane2];
            ax += v * xv.x; ay += v * xv.y;
        }
    }
    float* D = state_ptr(dst_id);
    *(float2*)&D[(size_t)row * 64 + lane2] = make_float2(ax, ay);
}

// ---------------- [rows,64] @ [64,64]^T + bias, 64-row tiles, 2 rows/thread ----------------
__device__ __forceinline__ void gemm64_body(const float* __restrict__ X,
                                            const float* __restrict__ W,
                                            const float* __restrict__ bias,
                                            float* __restrict__ Y, int nrows) {
    __shared__ float Wt[64][68];
    __shared__ float Xs[64][68];
    __shared__ float bs[64];
    int t = threadIdx.x;
    for (int i = t; i < 4096; i += 256) {
        int j = i >> 6, k = i & 63;
        Wt[k][j] = W[i];
    }
    if (t < 64) bs[t] = bias[t];
    int row0 = blockIdx.x * 64;
    for (int i = t; i < 1024; i += 256) {
        int r = i >> 4, q = i & 15;
        float4 v = make_float4(0.f, 0.f, 0.f, 0.f);
        if (row0 + r < nrows) v = *(const float4*)&X[(size_t)(row0 + r) * 64 + q * 4];
        *(float4*)&Xs[r][q * 4] = v;
    }
    __syncthreads();
    int nd = t >> 3;            // 0..31
    int cg = (t & 7) * 8;       // col group
    float acc0[8], acc1[8];
    #pragma unroll
    for (int j = 0; j < 8; j++) { acc0[j] = bs[cg + j]; acc1[j] = bs[cg + j]; }
    #pragma unroll
    for (int k = 0; k < 64; k++) {
        float x0 = Xs[nd][k];
        float x1 = Xs[nd + 32][k];
        float4 w0 = *(const float4*)&Wt[k][cg];
        float4 w1 = *(const float4*)&Wt[k][cg + 4];
        acc0[0] += x0 * w0.x; acc0[1] += x0 * w0.y; acc0[2] += x0 * w0.z; acc0[3] += x0 * w0.w;
        acc0[4] += x0 * w1.x; acc0[5] += x0 * w1.y; acc0[6] += x0 * w1.z; acc0[7] += x0 * w1.w;
        acc1[0] += x1 * w0.x; acc1[1] += x1 * w0.y; acc1[2] += x1 * w0.z; acc1[3] += x1 * w0.w;
        acc1[4] += x1 * w1.x; acc1[5] += x1 * w1.y; acc1[6] += x1 * w1.z; acc1[7] += x1 * w1.w;
    }
    int r0 = row0 + nd, r1 = row0 + nd + 32;
    if (r0 < nrows) {
        *(float4*)&Y[(size_t)r0 * 64 + cg]     = make_float4(acc0[0], acc0[1], acc0[2], acc0[3]);
        *(float4*)&Y[(size_t)r0 * 64 + cg + 4] = make_float4(acc0[4], acc0[5], acc0[6], acc0[7]);
    }
    if (r1 < nrows) {
        *(float4*)&Y[(size_t)r1 * 64 + cg]     = make_float4(acc1[0], acc1[1], acc1[2], acc1[3]);
        *(float4*)&Y[(size_t)r1 * 64 + cg + 4] = make_float4(acc1[4], acc1[5], acc1[6], acc1[7]);
    }
}

__global__ void proj_kernel(const float* __restrict__ f0, const float* __restrict__ f1,
                            const float* __restrict__ f2, const float* __restrict__ wsW,
                            const float* __restrict__ wsb) {
    int type = blockIdx.y;
    const float* X = (type == 0) ? f0 : (type == 1) ? f1 : f2;
    gemm64_body(X, wsW + (size_t)type * 4096, wsb + type * 64,
                g_hid + (size_t)type * NPT * 64, NPT);
}

__global__ void aff_kernel(const float* __restrict__ cW, const float* __restrict__ cb, int m) {
    gemm64_body(g_hid, cW + (size_t)m * 4096, cb + m * 64, g_s0, NN);
}

// layernorm + exact gelu + attention logit. 8 warps/block, one warp per node.
__global__ void post_kernel(const float* __restrict__ gvec, const float* __restrict__ bvec,
                            const float* __restrict__ A1, const float* __restrict__ b1,
                            const float* __restrict__ a2, const float* __restrict__ b2,
                            int meta) {
    __shared__ float A1s[64][68];
    __shared__ float hs[8][68];
    __shared__ float b1s[64];
    __shared__ float a2s[64];
    int t = threadIdx.x;
    for (int i = t; i < 4096; i += 256) {
        int a = i >> 6, k = i & 63;
        A1s[a][k] = A1[i];
    }
    if (t < 64) { b1s[t] = b1[t]; a2s[t] = a2[t]; }
    __syncthreads();

    int w = t >> 5;
    int lane = t & 31;
    int node = blockIdx.x * 8 + w;
    if (node >= NN) return;

    float* T = meta ? g_t1 : g_t0;
    const float* S = g_s3;

    float h0 = S[(size_t)node * 64 + lane];
    float h1 = S[(size_t)node * 64 + lane + 32];
    float mu = warp_sum(h0 + h1) * (1.0f / 64.0f);
    float d0 = h0 - mu, d1 = h1 - mu;
    float var = warp_sum(d0 * d0 + d1 * d1) * (1.0f / 64.0f);
    float rstd = rsqrtf(var + 1e-5f);
    float n0 = d0 * rstd * gvec[lane] + bvec[lane];
    float n1 = d1 * rstd * gvec[lane + 32] + bvec[lane + 32];
    float ge0 = 0.5f * n0 * (1.0f + erff(n0 * 0.70710678118654752f));
    float ge1 = 0.5f * n1 * (1.0f + erff(n1 * 0.70710678118654752f));
    T[(size_t)node * 64 + lane] = ge0;
    T[(size_t)node * 64 + lane + 32] = ge1;
    hs[w][lane] = ge0;
    hs[w][lane + 32] = ge1;
    __syncwarp();

    float part = 0.f;
    #pragma unroll
    for (int half = 0; half < 2; half++) {
        int a = lane + half * 32;
        float acc = b1s[a];
        #pragma unroll
        for (int k4 = 0; k4 < 16; k4++) {
            float4 wv = *(const float4*)&A1s[a][k4 * 4];
            float4 hv = *(const float4*)&hs[w][k4 * 4];
            acc += wv.x * hv.x + wv.y * hv.y + wv.z * hv.z + wv.w * hv.w;
        }
        part += tanhf(acc) * a2s[a];
    }
    part = warp_sum(part);
    if (lane == 0) g_logits[node * 2 + meta] = part + b2[0];
}

// 2-way softmax over metas + weighted sum -> out
__global__ void mix_kernel(float* __restrict__ out) {
    int idx = blockIdx.x * 256 + threadIdx.x;
    if (idx >= NN * 16) return;
    int node = idx >> 4, q = idx & 15;
    float l0 = g_logits[node * 2 + 0];
    float l1 = g_logits[node * 2 + 1];
    float mx = fmaxf(l0, l1);
    float e0 = expf(l0 - mx), e1 = expf(l1 - mx);
    float inv = 1.0f / (e0 + e1);
    float w0 = e0 * inv, w1 = e1 * inv;
    float4 a = *(const float4*)&g_t0[(size_t)node * 64 + q * 4];
    float4 b = *(const float4*)&g_t1[(size_t)node * 64 + q * 4];
    *(float4*)&out[(size_t)node * 64 + q * 4] =
        make_float4(w0 * a.x + w1 * b.x, w0 * a.y + w1 * b.y,
                    w0 * a.z + w1 * b.z, w0 * a.w + w1 * b.w);
}

extern "C" void kernel_launch(void* const* d_in, const int* in_sizes, int n_in,
                              void* d_out, int out_size) {
    const float* feats0      = (const float*)d_in[0];
    const float* feats1      = (const float*)d_in[1];
    const float* feats2      = (const float*)d_in[2];
    const float* ws_W        = (const float*)d_in[3];
    const float* ws_b        = (const float*)d_in[4];
    const float* adj_vals    = (const float*)d_in[5];
    const float* cell_aff_W  = (const float*)d_in[6];
    const float* cell_aff_b  = (const float*)d_in[7];
    const float* cell_norm_g = (const float*)d_in[8];
    const float* cell_norm_b = (const float*)d_in[9];
    const float* attn1_W     = (const float*)d_in[10];
    const float* attn1_b     = (const float*)d_in[11];
    const float* attn2_W     = (const float*)d_in[12];
    const float* attn2_b     = (const float*)d_in[13];
    // d_in[14] = node_types (contiguous blocks; unused)
    const int* adj_rows      = (const int*)d_in[15];
    const int* adj_cols      = (const int*)d_in[16];
    const int* idxes_seq     = (const int*)d_in[17];   // [2,3]
    const int* idxes_res     = (const int*)d_in[18];   // [2,3]
    float* out = (float*)d_out;

    const int GEMM_BLOCKS_ALL  = (NN + 63) / 64;       // 1547
    const int GEMM_BLOCKS_TYPE = (NPT + 63) / 64;      // 516
    const int EDGE4_BLOCKS = (NADJ * NNZC / 4 + 255) / 256;
    const int CNT_BLOCKS   = (NADJ * NN + 255) / 256;
    const int GATH_BLOCKS  = (NN * 32 + 255) / 256;
    const int POST_BLOCKS  = (NN + 7) / 8;
    const int MIX_BLOCKS   = (NN * 16 + 255) / 256;

    // ---- CSR build ----
    zero_counts_kernel<<<CNT_BLOCKS, 256>>>();
    hist_kernel<<<EDGE4_BLOCKS, 256>>>(adj_rows);
    scanA_kernel<<<dim3(NT, NADJ), 1024>>>();
    scanB_kernel<<<NADJ, 128>>>();
    scanC_kernel<<<dim3(NT, NADJ), 1024>>>();
    scatter_kernel<<<EDGE4_BLOCKS, 256>>>(adj_rows, adj_cols, adj_vals);

    // ---- type-wise projection -> g_hid ----
    proj_kernel<<<dim3(GEMM_BLOCKS_TYPE, 3), 256>>>(feats0, feats1, feats2, ws_W, ws_b);

    for (int m = 0; m < 2; m++) {
        const int* seq = idxes_seq + m * 3;
        const int* res = idxes_res + m * 3;

        aff_kernel<<<GEMM_BLOCKS_ALL, 256>>>(cell_aff_W, cell_aff_b, m);

        spmm_gather_kernel<<<GATH_BLOCKS, 256>>>(1, 0, seq + 0, 0, seq + 0, 0, seq + 0, 1);
        spmm_gather_kernel<<<GATH_BLOCKS, 256>>>(2, 1, seq + 1, 0, res + 0, 0, res + 0, 2);
        spmm_gather_kernel<<<GATH_BLOCKS, 256>>>(3, 2, seq + 2, 0, res + 1, 1, res + 2, 3);

        post_kernel<<<POST_BLOCKS, 256>>>(cell_norm_g + m * 64, cell_norm_b + m * 64,
                                          attn1_W, attn1_b, attn2_W, attn2_b, m);
    }

    mix_kernel<<<MIX_BLOCKS, 256>>>(out);
}

// round 5
// speedup vs baseline: 1.7012x; 1.0837x over previous
#include <cuda_runtime.h>
#include <cuda_fp16.h>
#include <math.h>

#define NN   99000
#define NH   64
#define NNZC 1584000
#define NADJ 6
#define NPT  33000
#define NT   97          // scan tiles per adjacency: ceil(99000/1024)

// ---------------- scratch (device globals; no runtime allocation) ----------------
__device__ float  g_hid[NN * NH];        // fp32 input projection
__device__ __half g_h0[NN * NH];         // fp16 state s0
__device__ __half g_h1[NN * NH];         // fp16 state s1
__device__ __half g_h2[NN * NH];         // fp16 state s2
__device__ float  g_s3[NN * NH];         // fp32 final state
__device__ float  g_t0[NN * NH];
__device__ float  g_t1[NN * NH];
__device__ float  g_logits[NN * 2];

// CSR scratch
__device__ int  g_cursor[NADJ * NN];
__device__ int  g_rowptr[NADJ * (NN + 1)];
__device__ int  g_tilesum[NADJ * NT];
__device__ int  g_tileoff[NADJ * NT];
__device__ int2 g_pack[(size_t)NADJ * NNZC];  // (col, val bits) sorted by row

__device__ __forceinline__ const __half* half_state(int id) {
    switch (id) {
        case 0: return g_h0;
        case 1: return g_h1;
        default: return g_h2;
    }
}

__device__ __forceinline__ float warp_sum(float v) {
    #pragma unroll
    for (int o = 16; o > 0; o >>= 1) v += __shfl_xor_sync(0xffffffffu, v, o);
    return v;
}

// ---------------- CSR build ----------------
__global__ void zero_counts_kernel() {
    int i = blockIdx.x * 256 + threadIdx.x;
    if (i < NADJ * NN) g_cursor[i] = 0;
}

// 8 edges per thread (2x int4 loads) for atomic MLP
__global__ void hist_kernel(const int* __restrict__ rows) {
    int i = blockIdx.x * 256 + threadIdx.x;
    if (i >= NADJ * NNZC / 8) return;
    int a = (i * 8) / NNZC;
    int4 r0 = *(const int4*)&rows[i * 8];
    int4 r1 = *(const int4*)&rows[i * 8 + 4];
    int* cnt = g_cursor + a * NN;
    atomicAdd(&cnt[r0.x], 1); atomicAdd(&cnt[r0.y], 1);
    atomicAdd(&cnt[r0.z], 1); atomicAdd(&cnt[r0.w], 1);
    atomicAdd(&cnt[r1.x], 1); atomicAdd(&cnt[r1.y], 1);
    atomicAdd(&cnt[r1.z], 1); atomicAdd(&cnt[r1.w], 1);
}

// phase A: per-tile local exclusive scan (1024 threads), tile totals out
__global__ void scanA_kernel() {
    __shared__ int sh[32];
    int a = blockIdx.y, tile = blockIdx.x;
    int idx = tile * 1024 + threadIdx.x;
    int lane = threadIdx.x & 31, wid = threadIdx.x >> 5;
    int v = (idx < NN) ? g_cursor[a * NN + idx] : 0;
    int s = v;
    #pragma unroll
    for (int o = 1; o < 32; o <<= 1) {
        int n = __shfl_up_sync(0xffffffffu, s, o);
        if (lane >= o) s += n;
    }
    if (lane == 31) sh[wid] = s;
    __syncthreads();
    if (wid == 0) {
        int w = sh[lane];
        #pragma unroll
        for (int o = 1; o < 32; o <<= 1) {
            int n = __shfl_up_sync(0xffffffffu, w, o);
            if (lane >= o) w += n;
        }
        sh[lane] = w;
    }
    __syncthreads();
    int incl = s + ((wid > 0) ? sh[wid - 1] : 0);
    if (idx < NN) g_rowptr[a * (NN + 1) + idx] = incl - v;
    if (threadIdx.x == 1023) g_tilesum[a * NT + tile] = incl;
}

// phase B: scan tile sums per adjacency
__global__ void scanB_kernel() {
    __shared__ int sh[4];
    int a = blockIdx.x, t = threadIdx.x;
    int lane = t & 31, wid = t >> 5;
    int orig = (t < NT) ? g_tilesum[a * NT + t] : 0;
    int s = orig;
    #pragma unroll
    for (int o = 1; o < 32; o <<= 1) {
        int n = __shfl_up_sync(0xffffffffu, s, o);
        if (lane >= o) s += n;
    }
    if (lane == 31) sh[wid] = s;
    __syncthreads();
    int add = 0;
    for (int w = 0; w < wid; w++) add += sh[w];
    int incl = s + add;
    if (t < NT) g_tileoff[a * NT + t] = incl - orig;
    if (t == NT - 1) g_rowptr[a * (NN + 1) + NN] = incl;
}

// phase C: add tile offsets; produce final rowptr and cursor copy
__global__ void scanC_kernel() {
    int a = blockIdx.y;
    int idx = blockIdx.x * 1024 + threadIdx.x;
    if (idx >= NN) return;
    int off = g_tileoff[a * NT + blockIdx.x];
    int e = g_rowptr[a * (NN + 1) + idx] + off;
    g_rowptr[a * (NN + 1) + idx] = e;
    g_cursor[a * NN + idx] = e;
}

// 8 edges per thread
__global__ void scatter_kernel(const int* __restrict__ rows, const int* __restrict__ cols,
                               const float* __restrict__ vals) {
    int i = blockIdx.x * 256 + threadIdx.x;
    if (i >= NADJ * NNZC / 8) return;
    int a = (i * 8) / NNZC;
    int* cur = g_cursor + a * NN;
    int2* pk = (int2*)(g_pack + (size_t)a * NNZC);
    #pragma unroll
    for (int h = 0; h < 2; h++) {
        int base = i * 8 + h * 4;
        int4 r = *(const int4*)&rows[base];
        int4 c = *(const int4*)&cols[base];
        float4 v = *(const float4*)&vals[base];
        int p0 = atomicAdd(&cur[r.x], 1);
        int p1 = atomicAdd(&cur[r.y], 1);
        int p2 = atomicAdd(&cur[r.z], 1);
        int p3 = atomicAdd(&cur[r.w], 1);
        pk[p0] = make_int2(c.x, __float_as_int(v.x));
        pk[p1] = make_int2(c.y, __float_as_int(v.y));
        pk[p2] = make_int2(c.z, __float_as_int(v.z));
        pk[p3] = make_int2(c.w, __float_as_int(v.w));
    }
}

// ---------------- fused gather SpMM (fp16 sources, fp32 accumulate) ----------------
// one warp per row; each lane owns 2 of the 64 columns (one __half2 per edge).
// NP pairs accumulated. dst_id: 0..2 = fp16 states, 3 = fp32 g_s3.
template<int NP>
__global__ void spmm_gather_kernel(int src0, const int* a0,
                                   int src1, const int* a1,
                                   int src2, const int* a2, int dst_id) {
    int gid = blockIdx.x * 256 + threadIdx.x;
    int row = gid >> 5;
    if (row >= NN) return;
    int lane2 = (threadIdx.x & 31) * 2;

    float ax = 0.f, ay = 0.f;
    #pragma unroll
    for (int p = 0; p < NP; p++) {
        int src = (p == 0) ? src0 : (p == 1) ? src1 : src2;
        const int* ap = (p == 0) ? a0 : (p == 1) ? a1 : a2;
        int aidx = *ap;
        const __half* __restrict__ S = half_state(src);
        const int* rp = g_rowptr + aidx * (NN + 1);
        int j   = rp[row];
        int end = rp[row + 1];
        const int2* __restrict__ pk = g_pack + (size_t)aidx * NNZC;

        for (; j + 8 <= end; j += 8) {
            int2 e0 = pk[j],     e1 = pk[j + 1], e2 = pk[j + 2], e3 = pk[j + 3];
            int2 e4 = pk[j + 4], e5 = pk[j + 5], e6 = pk[j + 6], e7 = pk[j + 7];
            float2 x0 = __half22float2(*(const __half2*)&S[(size_t)e0.x * 64 + lane2]);
            float2 x1 = __half22float2(*(const __half2*)&S[(size_t)e1.x * 64 + lane2]);
            float2 x2 = __half22float2(*(const __half2*)&S[(size_t)e2.x * 64 + lane2]);
            float2 x3 = __half22float2(*(const __half2*)&S[(size_t)e3.x * 64 + lane2]);
            float2 x4 = __half22float2(*(const __half2*)&S[(size_t)e4.x * 64 + lane2]);
            float2 x5 = __half22float2(*(const __half2*)&S[(size_t)e5.x * 64 + lane2]);
            float2 x6 = __half22float2(*(const __half2*)&S[(size_t)e6.x * 64 + lane2]);
            float2 x7 = __half22float2(*(const __half2*)&S[(size_t)e7.x * 64 + lane2]);
            ax += __int_as_float(e0.y) * x0.x; ay += __int_as_float(e0.y) * x0.y;
            ax += __int_as_float(e1.y) * x1.x; ay += __int_as_float(e1.y) * x1.y;
            ax += __int_as_float(e2.y) * x2.x; ay += __int_as_float(e2.y) * x2.y;
            ax += __int_as_float(e3.y) * x3.x; ay += __int_as_float(e3.y) * x3.y;
            ax += __int_as_float(e4.y) * x4.x; ay += __int_as_float(e4.y) * x4.y;
            ax += __int_as_float(e5.y) * x5.x; ay += __int_as_float(e5.y) * x5.y;
            ax += __int_as_float(e6.y) * x6.x; ay += __int_as_float(e6.y) * x6.y;
            ax += __int_as_float(e7.y) * x7.x; ay += __int_as_float(e7.y) * x7.y;
        }
        for (; j + 4 <= end; j += 4) {
            int2 e0 = pk[j], e1 = pk[j + 1], e2 = pk[j + 2], e3 = pk[j + 3];
            float2 x0 = __half22float2(*(const __half2*)&S[(size_t)e0.x * 64 + lane2]);
            float2 x1 = __half22float2(*(const __half2*)&S[(size_t)e1.x * 64 + lane2]);
            float2 x2 = __half22float2(*(const __half2*)&S[(size_t)e2.x * 64 + lane2]);
            float2 x3 = __half22float2(*(const __half2*)&S[(size_t)e3.x * 64 + lane2]);
            ax += __int_as_float(e0.y) * x0.x; ay += __int_as_float(e0.y) * x0.y;
            ax += __int_as_float(e1.y) * x1.x; ay += __int_as_float(e1.y) * x1.y;
            ax += __int_as_float(e2.y) * x2.x; ay += __int_as_float(e2.y) * x2.y;
            ax += __int_as_float(e3.y) * x3.x; ay += __int_as_float(e3.y) * x3.y;
        }
        for (; j < end; j++) {
            int2 e = pk[j];
            float v = __int_as_float(e.y);
            float2 xv = __half22float2(*(const __half2*)&S[(size_t)e.x * 64 + lane2]);
            ax += v * xv.x; ay += v * xv.y;
        }
    }
    if (dst_id == 3) {
        *(float2*)&g_s3[(size_t)row * 64 + lane2] = make_float2(ax, ay);
    } else {
        __half* D = (__half*)half_state(dst_id);
        *(__half2*)&D[(size_t)row * 64 + lane2] = __floats2half2_rn(ax, ay);
    }
}

// ---------------- [rows,64] @ [64,64]^T + bias, 64-row tiles, 2 rows/thread ----------------
// HALF_OUT: write fp16 into g_h0 (ignores Yf)
template<bool HALF_OUT>
__device__ __forceinline__ void gemm64_body(const float* __restrict__ X,
                                            const float* __restrict__ W,
                                            const float* __restrict__ bias,
                                            float* __restrict__ Yf, int nrows) {
    __shared__ float Wt[64][68];
    __shared__ float Xs[64][68];
    __shared__ float bs[64];
    int t = threadIdx.x;
    for (int i = t; i < 4096; i += 256) {
        int j = i >> 6, k = i & 63;
        Wt[k][j] = W[i];
    }
    if (t < 64) bs[t] = bias[t];
    int row0 = blockIdx.x * 64;
    for (int i = t; i < 1024; i += 256) {
        int r = i >> 4, q = i & 15;
        float4 v = make_float4(0.f, 0.f, 0.f, 0.f);
        if (row0 + r < nrows) v = *(const float4*)&X[(size_t)(row0 + r) * 64 + q * 4];
        *(float4*)&Xs[r][q * 4] = v;
    }
    __syncthreads();
    int nd = t >> 3;
    int cg = (t & 7) * 8;
    float acc0[8], acc1[8];
    #pragma unroll
    for (int j = 0; j < 8; j++) { acc0[j] = bs[cg + j]; acc1[j] = bs[cg + j]; }
    #pragma unroll
    for (int k = 0; k < 64; k++) {
        float x0 = Xs[nd][k];
        float x1 = Xs[nd + 32][k];
        float4 w0 = *(const float4*)&Wt[k][cg];
        float4 w1 = *(const float4*)&Wt[k][cg + 4];
        acc0[0] += x0 * w0.x; acc0[1] += x0 * w0.y; acc0[2] += x0 * w0.z; acc0[3] += x0 * w0.w;
        acc0[4] += x0 * w1.x; acc0[5] += x0 * w1.y; acc0[6] += x0 * w1.z; acc0[7] += x0 * w1.w;
        acc1[0] += x1 * w0.x; acc1[1] += x1 * w0.y; acc1[2] += x1 * w0.z; acc1[3] += x1 * w0.w;
        acc1[4] += x1 * w1.x; acc1[5] += x1 * w1.y; acc1[6] += x1 * w1.z; acc1[7] += x1 * w1.w;
    }
    int r0 = row0 + nd, r1 = row0 + nd + 32;
    if (HALF_OUT) {
        if (r0 < nrows) {
            __half2* yp = (__half2*)&g_h0[(size_t)r0 * 64 + cg];
            yp[0] = __floats2half2_rn(acc0[0], acc0[1]);
            yp[1] = __floats2half2_rn(acc0[2], acc0[3]);
            yp[2] = __floats2half2_rn(acc0[4], acc0[5]);
            yp[3] = __floats2half2_rn(acc0[6], acc0[7]);
        }
        if (r1 < nrows) {
            __half2* yp = (__half2*)&g_h0[(size_t)r1 * 64 + cg];
            yp[0] = __floats2half2_rn(acc1[0], acc1[1]);
            yp[1] = __floats2half2_rn(acc1[2], acc1[3]);
            yp[2] = __floats2half2_rn(acc1[4], acc1[5]);
            yp[3] = __floats2half2_rn(acc1[6], acc1[7]);
        }
    } else {
        if (r0 < nrows) {
            *(float4*)&Yf[(size_t)r0 * 64 + cg]     = make_float4(acc0[0], acc0[1], acc0[2], acc0[3]);
            *(float4*)&Yf[(size_t)r0 * 64 + cg + 4] = make_float4(acc0[4], acc0[5], acc0[6], acc0[7]);
        }
        if (r1 < nrows) {
            *(float4*)&Yf[(size_t)r1 * 64 + cg]     = make_float4(acc1[0], acc1[1], acc1[2], acc1[3]);
            *(float4*)&Yf[(size_t)r1 * 64 + cg + 4] = make_float4(acc1[4], acc1[5], acc1[6], acc1[7]);
        }
    }
}

__global__ void proj_kernel(const float* __restrict__ f0, const float* __restrict__ f1,
                            const float* __restrict__ f2, const float* __restrict__ wsW,
                            const float* __restrict__ wsb) {
    int type = blockIdx.y;
    const float* X = (type == 0) ? f0 : (type == 1) ? f1 : f2;
    gemm64_body<false>(X, wsW + (size_t)type * 4096, wsb + type * 64,
                       g_hid + (size_t)type * NPT * 64, NPT);
}

// cell affine -> s0 stored fp16 (g_h0)
__global__ void aff_kernel(const float* __restrict__ cW, const float* __restrict__ cb, int m) {
    gemm64_body<true>(g_hid, cW + (size_t)m * 4096, cb + m * 64, nullptr, NN);
}

// layernorm + exact gelu + attention logit. 8 warps/block, one warp per node.
__global__ void post_kernel(const float* __restrict__ gvec, const float* __restrict__ bvec,
                            const float* __restrict__ A1, const float* __restrict__ b1,
                            const float* __restrict__ a2, const float* __restrict__ b2,
                            int meta) {
    __shared__ float A1s[64][68];
    __shared__ float hs[8][68];
    __shared__ float b1s[64];
    __shared__ float a2s[64];
    int t = threadIdx.x;
    for (int i = t; i < 4096; i += 256) {
        int a = i >> 6, k = i & 63;
        A1s[a][k] = A1[i];
    }
    if (t < 64) { b1s[t] = b1[t]; a2s[t] = a2[t]; }
    __syncthreads();

    int w = t >> 5;
    int lane = t & 31;
    int node = blockIdx.x * 8 + w;
    if (node >= NN) return;

    float* T = meta ? g_t1 : g_t0;
    const float* S = g_s3;

    float h0 = S[(size_t)node * 64 + lane];
    float h1 = S[(size_t)node * 64 + lane + 32];
    float mu = warp_sum(h0 + h1) * (1.0f / 64.0f);
    float d0 = h0 - mu, d1 = h1 - mu;
    float var = warp_sum(d0 * d0 + d1 * d1) * (1.0f / 64.0f);
    float rstd = rsqrtf(var + 1e-5f);
    float n0 = d0 * rstd * gvec[lane] + bvec[lane];
    float n1 = d1 * rstd * gvec[lane + 32] + bvec[lane + 32];
    float ge0 = 0.5f * n0 * (1.0f + erff(n0 * 0.70710678118654752f));
    float ge1 = 0.5f * n1 * (1.0f + erff(n1 * 0.70710678118654752f));
    T[(size_t)node * 64 + lane] = ge0;
    T[(size_t)node * 64 + lane + 32] = ge1;
    hs[w][lane] = ge0;
    hs[w][lane + 32] = ge1;
    __syncwarp();

    float part = 0.f;
    #pragma unroll
    for (int half = 0; half < 2; half++) {
        int a = lane + half * 32;
        float acc = b1s[a];
        #pragma unroll
        for (int k4 = 0; k4 < 16; k4++) {
            float4 wv = *(const float4*)&A1s[a][k4 * 4];
            float4 hv = *(const float4*)&hs[w][k4 * 4];
            acc += wv.x * hv.x + wv.y * hv.y + wv.z * hv.z + wv.w * hv.w;
        }
        part += tanhf(acc) * a2s[a];
    }
    part = warp_sum(part);
    if (lane == 0) g_logits[node * 2 + meta] = part + b2[0];
}

// 2-way softmax over metas + weighted sum -> out
__global__ void mix_kernel(float* __restrict__ out) {
    int idx = blockIdx.x * 256 + threadIdx.x;
    if (idx >= NN * 16) return;
    int node = idx >> 4, q = idx & 15;
    float l0 = g_logits[node * 2 + 0];
    float l1 = g_logits[node * 2 + 1];
    float mx = fmaxf(l0, l1);
    float e0 = expf(l0 - mx), e1 = expf(l1 - mx);
    float inv = 1.0f / (e0 + e1);
    float w0 = e0 * inv, w1 = e1 * inv;
    float4 a = *(const float4*)&g_t0[(size_t)node * 64 + q * 4];
    float4 b = *(const float4*)&g_t1[(size_t)node * 64 + q * 4];
    *(float4*)&out[(size_t)node * 64 + q * 4] =
        make_float4(w0 * a.x + w1 * b.x, w0 * a.y + w1 * b.y,
                    w0 * a.z + w1 * b.z, w0 * a.w + w1 * b.w);
}

extern "C" void kernel_launch(void* const* d_in, const int* in_sizes, int n_in,
                              void* d_out, int out_size) {
    const float* feats0      = (const float*)d_in[0];
    const float* feats1      = (const float*)d_in[1];
    const float* feats2      = (const float*)d_in[2];
    const float* ws_W        = (const float*)d_in[3];
    const float* ws_b        = (const float*)d_in[4];
    const float* adj_vals    = (const float*)d_in[5];
    const float* cell_aff_W  = (const float*)d_in[6];
    const float* cell_aff_b  = (const float*)d_in[7];
    const float* cell_norm_g = (const float*)d_in[8];
    const float* cell_norm_b = (const float*)d_in[9];
    const float* attn1_W     = (const float*)d_in[10];
    const float* attn1_b     = (const float*)d_in[11];
    const float* attn2_W     = (const float*)d_in[12];
    const float* attn2_b     = (const float*)d_in[13];
    // d_in[14] = node_types (contiguous blocks; unused)
    const int* adj_rows      = (const int*)d_in[15];
    const int* adj_cols      = (const int*)d_in[16];
    const int* idxes_seq     = (const int*)d_in[17];   // [2,3]
    const int* idxes_res     = (const int*)d_in[18];   // [2,3]
    float* out = (float*)d_out;

    const int GEMM_BLOCKS_ALL  = (NN + 63) / 64;
    const int GEMM_BLOCKS_TYPE = (NPT + 63) / 64;
    const int EDGE8_BLOCKS = (NADJ * NNZC / 8 + 255) / 256;
    const int CNT_BLOCKS   = (NADJ * NN + 255) / 256;
    const int GATH_BLOCKS  = (NN * 32 + 255) / 256;
    const int POST_BLOCKS  = (NN + 7) / 8;
    const int MIX_BLOCKS   = (NN * 16 + 255) / 256;

    // ---- CSR build ----
    zero_counts_kernel<<<CNT_BLOCKS, 256>>>();
    hist_kernel<<<EDGE8_BLOCKS, 256>>>(adj_rows);
    scanA_kernel<<<dim3(NT, NADJ), 1024>>>();
    scanB_kernel<<<NADJ, 128>>>();
    scanC_kernel<<<dim3(NT, NADJ), 1024>>>();
    scatter_kernel<<<EDGE8_BLOCKS, 256>>>(adj_rows, adj_cols, adj_vals);

    // ---- type-wise projection -> g_hid (fp32) ----
    proj_kernel<<<dim3(GEMM_BLOCKS_TYPE, 3), 256>>>(feats0, feats1, feats2, ws_W, ws_b);

    for (int m = 0; m < 2; m++) {
        const int* seq = idxes_seq + m * 3;
        const int* res = idxes_res + m * 3;

        // states[0] = hid @ cell_aff_W[m]^T + b  -> fp16 s0
        aff_kernel<<<GEMM_BLOCKS_ALL, 256>>>(cell_aff_W, cell_aff_b, m);

        // states[1] = spmm(seq0, s0) -> fp16 s1
        spmm_gather_kernel<1><<<GATH_BLOCKS, 256>>>(0, seq + 0, 0, seq + 0, 0, seq + 0, 1);
        // states[2] = spmm(seq1, s1) + spmm(res0, s0) -> fp16 s2
        spmm_gather_kernel<2><<<GATH_BLOCKS, 256>>>(1, seq + 1, 0, res + 0, 0, res + 0, 2);
        // states[3] = spmm(seq2, s2) + spmm(res1, s0) + spmm(res2, s1) -> fp32 s3
        spmm_gather_kernel<3><<<GATH_BLOCKS, 256>>>(2, seq + 2, 0, res + 1, 1, res + 2, 3);

        post_kernel<<<POST_BLOCKS, 256>>>(cell_norm_g + m * 64, cell_norm_b + m * 64,
                                          attn1_W, attn1_b, attn2_W, attn2_b, m);
    }

    mix_kernel<<<MIX_BLOCKS, 256>>>(out);
}

// round 8
// speedup vs baseline: 1.7946x; 1.0549x over previous
#include <cuda_runtime.h>
#include <cuda_fp16.h>
#include <math.h>

#define NN   99000
#define NH   64
#define NNZC 1584000
#define NADJ 6
#define NPT  33000
#define NT   97          // scan tiles per adjacency: ceil(99000/1024)

// ---------------- scratch (device globals; no runtime allocation) ----------------
__device__ __half g_st[2][3][NN * NH];   // fp16 states s0,s1,s2 per meta
__device__ float  g_s3[2][NN * NH];      // fp32 final state per meta
__device__ float  g_t[2][NN * NH];       // gelu output per meta
__device__ float  g_logits[NN * 2];
__device__ float  g_Wc[2][3][NH * NH];   // composed weights, stored transposed: [k_in*64 + i_out]
__device__ float  g_bc[2][3][NH];        // composed biases

// CSR scratch
__device__ int  g_cursor[NADJ * NN];
__device__ int  g_rowptr[NADJ * (NN + 1)];
__device__ int  g_tilesum[NADJ * NT];
__device__ int  g_tileoff[NADJ * NT];
__device__ int2 g_pack[(size_t)NADJ * NNZC];  // (col, val bits) sorted by row

__device__ __forceinline__ const __half* st_ptr(int m, int id) {
    return g_st[m][id];
}

__device__ __forceinline__ float warp_sum(float v) {
    #pragma unroll
    for (int o = 16; o > 0; o >>= 1) v += __shfl_xor_sync(0xffffffffu, v, o);
    return v;
}

// ---------------- CSR build ----------------
__global__ void zero_counts_kernel() {
    int i = blockIdx.x * 256 + threadIdx.x;
    if (i < NADJ * NN) g_cursor[i] = 0;
}

__global__ void hist_kernel(const int* __restrict__ rows) {
    int i = blockIdx.x * 256 + threadIdx.x;
    if (i >= NADJ * NNZC / 8) return;
    int a = (i * 8) / NNZC;
    int4 r0 = *(const int4*)&rows[i * 8];
    int4 r1 = *(const int4*)&rows[i * 8 + 4];
    int* cnt = g_cursor + a * NN;
    atomicAdd(&cnt[r0.x], 1); atomicAdd(&cnt[r0.y], 1);
    atomicAdd(&cnt[r0.z], 1); atomicAdd(&cnt[r0.w], 1);
    atomicAdd(&cnt[r1.x], 1); atomicAdd(&cnt[r1.y], 1);
    atomicAdd(&cnt[r1.z], 1); atomicAdd(&cnt[r1.w], 1);
}

__global__ void scanA_kernel() {
    __shared__ int sh[32];
    int a = blockIdx.y, tile = blockIdx.x;
    int idx = tile * 1024 + threadIdx.x;
    int lane = threadIdx.x & 31, wid = threadIdx.x >> 5;
    int v = (idx < NN) ? g_cursor[a * NN + idx] : 0;
    int s = v;
    #pragma unroll
    for (int o = 1; o < 32; o <<= 1) {
        int n = __shfl_up_sync(0xffffffffu, s, o);
        if (lane >= o) s += n;
    }
    if (lane == 31) sh[wid] = s;
    __syncthreads();
    if (wid == 0) {
        int w = sh[lane];
        #pragma unroll
        for (int o = 1; o < 32; o <<= 1) {
            int n = __shfl_up_sync(0xffffffffu, w, o);
            if (lane >= o) w += n;
        }
        sh[lane] = w;
    }
    __syncthreads();
    int incl = s + ((wid > 0) ? sh[wid - 1] : 0);
    if (idx < NN) g_rowptr[a * (NN + 1) + idx] = incl - v;
    if (threadIdx.x == 1023) g_tilesum[a * NT + tile] = incl;
}

__global__ void scanB_kernel() {
    __shared__ int sh[4];
    int a = blockIdx.x, t = threadIdx.x;
    int lane = t & 31, wid = t >> 5;
    int orig = (t < NT) ? g_tilesum[a * NT + t] : 0;
    int s = orig;
    #pragma unroll
    for (int o = 1; o < 32; o <<= 1) {
        int n = __shfl_up_sync(0xffffffffu, s, o);
        if (lane >= o) s += n;
    }
    if (lane == 31) sh[wid] = s;
    __syncthreads();
    int add = 0;
    for (int w = 0; w < wid; w++) add += sh[w];
    int incl = s + add;
    if (t < NT) g_tileoff[a * NT + t] = incl - orig;
    if (t == NT - 1) g_rowptr[a * (NN + 1) + NN] = incl;
}

__global__ void scanC_kernel() {
    int a = blockIdx.y;
    int idx = blockIdx.x * 1024 + threadIdx.x;
    if (idx >= NN) return;
    int off = g_tileoff[a * NT + blockIdx.x];
    int e = g_rowptr[a * (NN + 1) + idx] + off;
    g_rowptr[a * (NN + 1) + idx] = e;
    g_cursor[a * NN + idx] = e;
}

__global__ void scatter_kernel(const int* __restrict__ rows, const int* __restrict__ cols,
                               const float* __restrict__ vals) {
    int i = blockIdx.x * 256 + threadIdx.x;
    if (i >= NADJ * NNZC / 8) return;
    int a = (i * 8) / NNZC;
    int* cur = g_cursor + a * NN;
    int2* pk = (int2*)(g_pack + (size_t)a * NNZC);
    #pragma unroll
    for (int h = 0; h < 2; h++) {
        int base = i * 8 + h * 4;
        int4 r = *(const int4*)&rows[base];
        int4 c = *(const int4*)&cols[base];
        float4 v = *(const float4*)&vals[base];
        int p0 = atomicAdd(&cur[r.x], 1);
        int p1 = atomicAdd(&cur[r.y], 1);
        int p2 = atomicAdd(&cur[r.z], 1);
        int p3 = atomicAdd(&cur[r.w], 1);
        pk[p0] = make_int2(c.x, __float_as_int(v.x));
        pk[p1] = make_int2(c.y, __float_as_int(v.y));
        pk[p2] = make_int2(c.z, __float_as_int(v.z));
        pk[p3] = make_int2(c.w, __float_as_int(v.w));
    }
}

// ---------------- weight composition: Wc[m][t] = cellW[m] @ wsW[t]  ----------------
// stored transposed (Wt layout): g_Wc[m][t][k*64 + i] = Wc[i][k]
// bc[m][t][i] = sum_k cellW[m][i][k] * ws_b[t][k] + cb[m][i]
__global__ void wcomb_kernel(const float* __restrict__ cW, const float* __restrict__ cb,
                             const float* __restrict__ wsW, const float* __restrict__ wsb) {
    __shared__ float cs[64][65];
    __shared__ float ws[64][65];
    int blk = blockIdx.x;
    int m = blk / 3;
    int t = blk % 3;
    int tid = threadIdx.x;
    for (int i = tid; i < 4096; i += 256) {
        int r = i >> 6, c = i & 63;
        cs[r][c] = cW[m * 4096 + i];   // cellW[m][r][c]
        ws[r][c] = wsW[t * 4096 + i];  // wsW[t][r][c]
    }
    __syncthreads();
    for (int e = tid; e < 4096; e += 256) {
        int i = e >> 6, k = e & 63;
        float acc = 0.f;
        #pragma unroll
        for (int q = 0; q < 64; q++) acc += cs[i][q] * ws[q][k];
        g_Wc[m][t][k * 64 + i] = acc;   // transposed store
    }
    if (tid < 64) {
        float acc = cb[m * 64 + tid];
        #pragma unroll
        for (int q = 0; q < 64; q++) acc += cs[tid][q] * wsb[t * 64 + q];
        g_bc[m][t][tid] = acc;
    }
}

// ---------------- fused s0: both metas from feats directly ----------------
// grid (tiles_of_64_rows_per_type, 3 types); X loaded once, two weight phases.
__global__ void s0_kernel(const float* __restrict__ f0, const float* __restrict__ f1,
                          const float* __restrict__ f2) {
    __shared__ float Xs[64][68];   // 68-float row stride: 272B, 16B-aligned
    __shared__ float Wt[64][64];   // Wt[k][j]
    __shared__ float bs[64];
    int type = blockIdx.y;
    const float* X = (type == 0) ? f0 : (type == 1) ? f1 : f2;
    int t = threadIdx.x;
    int lrow0 = blockIdx.x * 64;   // local row within type
    for (int i = t; i < 1024; i += 256) {
        int r = i >> 4, q = i & 15;
        float4 v = make_float4(0.f, 0.f, 0.f, 0.f);
        if (lrow0 + r < NPT) v = *(const float4*)&X[(size_t)(lrow0 + r) * 64 + q * 4];
        *(float4*)&Xs[r][q * 4] = v;
    }
    int nd = t >> 3;
    int cg = (t & 7) * 8;
    #pragma unroll
    for (int m = 0; m < 2; m++) {
        __syncthreads();
        for (int i = t; i < 4096; i += 256) ((float*)Wt)[i] = g_Wc[m][type][i];
        if (t < 64) bs[t] = g_bc[m][type][t];
        __syncthreads();
        float acc0[8], acc1[8];
        #pragma unroll
        for (int j = 0; j < 8; j++) { acc0[j] = bs[cg + j]; acc1[j] = bs[cg + j]; }
        #pragma unroll
        for (int k = 0; k < 64; k++) {
            float x0 = Xs[nd][k];
            float x1 = Xs[nd + 32][k];
            float4 w0 = *(const float4*)&Wt[k][cg];
            float4 w1 = *(const float4*)&Wt[k][cg + 4];
            acc0[0] += x0 * w0.x; acc0[1] += x0 * w0.y; acc0[2] += x0 * w0.z; acc0[3] += x0 * w0.w;
            acc0[4] += x0 * w1.x; acc0[5] += x0 * w1.y; acc0[6] += x0 * w1.z; acc0[7] += x0 * w1.w;
            acc1[0] += x1 * w0.x; acc1[1] += x1 * w0.y; acc1[2] += x1 * w0.z; acc1[3] += x1 * w0.w;
            acc1[4] += x1 * w1.x; acc1[5] += x1 * w1.y; acc1[6] += x1 * w1.z; acc1[7] += x1 * w1.w;
        }
        __half* D = (__half*)g_st[m][0];
        int r0 = type * NPT + lrow0 + nd;
        int r1 = r0 + 32;
        if (lrow0 + nd < NPT) {
            __half2* yp = (__half2*)&D[(size_t)r0 * 64 + cg];
            yp[0] = __floats2half2_rn(acc0[0], acc0[1]);
            yp[1] = __floats2half2_rn(acc0[2], acc0[3]);
            yp[2] = __floats2half2_rn(acc0[4], acc0[5]);
            yp[3] = __floats2half2_rn(acc0[6], acc0[7]);
        }
        if (lrow0 + nd + 32 < NPT) {
            __half2* yp = (__half2*)&D[(size_t)r1 * 64 + cg];
            yp[0] = __floats2half2_rn(acc1[0], acc1[1]);
            yp[1] = __floats2half2_rn(acc1[2], acc1[3]);
            yp[2] = __floats2half2_rn(acc1[4], acc1[5]);
            yp[3] = __floats2half2_rn(acc1[6], acc1[7]);
        }
    }
}

// ---------------- fused gather SpMM (fp16 sources, fp32 accumulate) ----------------
// grid.y = meta. one warp per row; each lane owns 2 of 64 columns.
// NP=1: s1 = A[seq0] s0;  NP=2: s2 = A[seq1] s1 + A[res0] s0
// NP=3: s3 = A[seq2] s2 + A[res1] s0 + A[res2] s1  (fp32 out)
template<int NP>
__global__ void spmm_gather_kernel(const int* __restrict__ idxes_seq,
                                   const int* __restrict__ idxes_res) {
    int m = blockIdx.y;
    int gid = blockIdx.x * 256 + threadIdx.x;
    int row = gid >> 5;
    if (row >= NN) return;
    int lane2 = (threadIdx.x & 31) * 2;
    const int* seq = idxes_seq + m * 3;
    const int* res = idxes_res + m * 3;

    float ax = 0.f, ay = 0.f;
    #pragma unroll
    for (int p = 0; p < NP; p++) {
        int src, aidx;
        if (NP == 1)      { src = 0; aidx = seq[0]; }
        else if (NP == 2) { src = (p == 0) ? 1 : 0; aidx = (p == 0) ? seq[1] : res[0]; }
        else              { src = (p == 0) ? 2 : (p == 1) ? 0 : 1;
                            aidx = (p == 0) ? seq[2] : (p == 1) ? res[1] : res[2]; }
        const __half* __restrict__ S = st_ptr(m, src);
        const int* rp = g_rowptr + aidx * (NN + 1);
        int j   = rp[row];
        int end = rp[row + 1];
        const int2* __restrict__ pk = g_pack + (size_t)aidx * NNZC;

        for (; j + 8 <= end; j += 8) {
            int2 e0 = pk[j],     e1 = pk[j + 1], e2 = pk[j + 2], e3 = pk[j + 3];
            int2 e4 = pk[j + 4], e5 = pk[j + 5], e6 = pk[j + 6], e7 = pk[j + 7];
            float2 x0 = __half22float2(*(const __half2*)&S[(size_t)e0.x * 64 + lane2]);
            float2 x1 = __half22float2(*(const __half2*)&S[(size_t)e1.x * 64 + lane2]);
            float2 x2 = __half22float2(*(const __half2*)&S[(size_t)e2.x * 64 + lane2]);
            float2 x3 = __half22float2(*(const __half2*)&S[(size_t)e3.x * 64 + lane2]);
            float2 x4 = __half22float2(*(const __half2*)&S[(size_t)e4.x * 64 + lane2]);
            float2 x5 = __half22float2(*(const __half2*)&S[(size_t)e5.x * 64 + lane2]);
            float2 x6 = __half22float2(*(const __half2*)&S[(size_t)e6.x * 64 + lane2]);
            float2 x7 = __half22float2(*(const __half2*)&S[(size_t)e7.x * 64 + lane2]);
            ax += __int_as_float(e0.y) * x0.x; ay += __int_as_float(e0.y) * x0.y;
            ax += __int_as_float(e1.y) * x1.x; ay += __int_as_float(e1.y) * x1.y;
            ax += __int_as_float(e2.y) * x2.x; ay += __int_as_float(e2.y) * x2.y;
            ax += __int_as_float(e3.y) * x3.x; ay += __int_as_float(e3.y) * x3.y;
            ax += __int_as_float(e4.y) * x4.x; ay += __int_as_float(e4.y) * x4.y;
            ax += __int_as_float(e5.y) * x5.x; ay += __int_as_float(e5.y) * x5.y;
            ax += __int_as_float(e6.y) * x6.x; ay += __int_as_float(e6.y) * x6.y;
            ax += __int_as_float(e7.y) * x7.x; ay += __int_as_float(e7.y) * x7.y;
        }
        for (; j + 4 <= end; j += 4) {
            int2 e0 = pk[j], e1 = pk[j + 1], e2 = pk[j + 2], e3 = pk[j + 3];
            float2 x0 = __half22float2(*(const __half2*)&S[(size_t)e0.x * 64 + lane2]);
            float2 x1 = __half22float2(*(const __half2*)&S[(size_t)e1.x * 64 + lane2]);
            float2 x2 = __half22float2(*(const __half2*)&S[(size_t)e2.x * 64 + lane2]);
            float2 x3 = __half22float2(*(const __half2*)&S[(size_t)e3.x * 64 + lane2]);
            ax += __int_as_float(e0.y) * x0.x; ay += __int_as_float(e0.y) * x0.y;
            ax += __int_as_float(e1.y) * x1.x; ay += __int_as_float(e1.y) * x1.y;
            ax += __int_as_float(e2.y) * x2.x; ay += __int_as_float(e2.y) * x2.y;
            ax += __int_as_float(e3.y) * x3.x; ay += __int_as_float(e3.y) * x3.y;
        }
        for (; j < end; j++) {
            int2 e = pk[j];
            float v = __int_as_float(e.y);
            float2 xv = __half22float2(*(const __half2*)&S[(size_t)e.x * 64 + lane2]);
            ax += v * xv.x; ay += v * xv.y;
        }
    }
    if (NP == 3) {
        *(float2*)&g_s3[m][(size_t)row * 64 + lane2] = make_float2(ax, ay);
    } else {
        __half* D = (__half*)st_ptr(m, NP);
        *(__half2*)&D[(size_t)row * 64 + lane2] = __floats2half2_rn(ax, ay);
    }
}

// ---------------- layernorm + exact gelu + attention logit; grid.y = meta ----------------
__global__ void post_kernel(const float* __restrict__ norm_g, const float* __restrict__ norm_b,
                            const float* __restrict__ A1, const float* __restrict__ b1,
                            const float* __restrict__ a2, const float* __restrict__ b2) {
    __shared__ float A1s[64][68];
    __shared__ float hs[8][68];
    __shared__ float b1s[64];
    __shared__ float a2s[64];
    int meta = blockIdx.y;
    const float* gvec = norm_g + meta * 64;
    const float* bvec = norm_b + meta * 64;
    int t = threadIdx.x;
    for (int i = t; i < 4096; i += 256) {
        int a = i >> 6, k = i & 63;
        A1s[a][k] = A1[i];
    }
    if (t < 64) { b1s[t] = b1[t]; a2s[t] = a2[t]; }
    __syncthreads();

    int w = t >> 5;
    int lane = t & 31;
    int node = blockIdx.x * 8 + w;
    if (node >= NN) return;

    float* T = g_t[meta];
    const float* S = g_s3[meta];

    float h0 = S[(size_t)node * 64 + lane];
    float h1 = S[(size_t)node * 64 + lane + 32];
    float mu = warp_sum(h0 + h1) * (1.0f / 64.0f);
    float d0 = h0 - mu, d1 = h1 - mu;
    float var = warp_sum(d0 * d0 + d1 * d1) * (1.0f / 64.0f);
    float rstd = rsqrtf(var + 1e-5f);
    float n0 = d0 * rstd * gvec[lane] + bvec[lane];
    float n1 = d1 * rstd * gvec[lane + 32] + bvec[lane + 32];
    float ge0 = 0.5f * n0 * (1.0f + erff(n0 * 0.70710678118654752f));
    float ge1 = 0.5f * n1 * (1.0f + erff(n1 * 0.70710678118654752f));
    T[(size_t)node * 64 + lane] = ge0;
    T[(size_t)node * 64 + lane + 32] = ge1;
    hs[w][lane] = ge0;
    hs[w][lane + 32] = ge1;
    __syncwarp();

    float part = 0.f;
    #pragma unroll
    for (int half = 0; half < 2; half++) {
        int a = lane + half * 32;
        float acc = b1s[a];
        #pragma unroll
        for (int k4 = 0; k4 < 16; k4++) {
            float4 wv = *(const float4*)&A1s[a][k4 * 4];
            float4 hv = *(const float4*)&hs[w][k4 * 4];
            acc += wv.x * hv.x + wv.y * hv.y + wv.z * hv.z + wv.w * hv.w;
        }
        part += tanhf(acc) * a2s[a];
    }
    part = warp_sum(part);
    if (lane == 0) g_logits[node * 2 + meta] = part + b2[0];
}

// ---------------- 2-way softmax over metas + weighted sum -> out ----------------
__global__ void mix_kernel(float* __restrict__ out) {
    int idx = blockIdx.x * 256 + threadIdx.x;
    if (idx >= NN * 16) return;
    int node = idx >> 4, q = idx & 15;
    float l0 = g_logits[node * 2 + 0];
    float l1 = g_logits[node * 2 + 1];
    float mx = fmaxf(l0, l1);
    float e0 = expf(l0 - mx), e1 = expf(l1 - mx);
    float inv = 1.0f / (e0 + e1);
    float w0 = e0 * inv, w1 = e1 * inv;
    float4 a = *(const float4*)&g_t[0][(size_t)node * 64 + q * 4];
    float4 b = *(const float4*)&g_t[1][(size_t)node * 64 + q * 4];
    *(float4*)&out[(size_t)node * 64 + q * 4] =
        make_float4(w0 * a.x + w1 * b.x, w0 * a.y + w1 * b.y,
                    w0 * a.z + w1 * b.z, w0 * a.w + w1 * b.w);
}

extern "C" void kernel_launch(void* const* d_in, const int* in_sizes, int n_in,
                              void* d_out, int out_size) {
    const float* feats0      = (const float*)d_in[0];
    const float* feats1      = (const float*)d_in[1];
    const float* feats2      = (const float*)d_in[2];
    const float* ws_W        = (const float*)d_in[3];
    const float* ws_b        = (const float*)d_in[4];
    const float* adj_vals    = (const float*)d_in[5];
    const float* cell_aff_W  = (const float*)d_in[6];
    const float* cell_aff_b  = (const float*)d_in[7];
    const float* cell_norm_g = (const float*)d_in[8];
    const float* cell_norm_b = (const float*)d_in[9];
    const float* attn1_W     = (const float*)d_in[10];
    const float* attn1_b     = (const float*)d_in[11];
    const float* attn2_W     = (const float*)d_in[12];
    const float* attn2_b     = (const float*)d_in[13];
    // d_in[14] = node_types (contiguous blocks; unused)
    const int* adj_rows      = (const int*)d_in[15];
    const int* adj_cols      = (const int*)d_in[16];
    const int* idxes_seq     = (const int*)d_in[17];   // [2,3]
    const int* idxes_res     = (const int*)d_in[18];   // [2,3]
    float* out = (float*)d_out;

    const int S0_BLOCKS    = (NPT + 63) / 64;          // 516 per type
    const int EDGE8_BLOCKS = (NADJ * NNZC / 8 + 255) / 256;
    const int CNT_BLOCKS   = (NADJ * NN + 255) / 256;
    const int GATH_BLOCKS  = (NN * 32 + 255) / 256;
    const int POST_BLOCKS  = (NN + 7) / 8;
    const int MIX_BLOCKS   = (NN * 16 + 255) / 256;

    // ---- CSR build ----
    zero_counts_kernel<<<CNT_BLOCKS, 256>>>();
    hist_kernel<<<EDGE8_BLOCKS, 256>>>(adj_rows);
    scanA_kernel<<<dim3(NT, NADJ), 1024>>>();
    scanB_kernel<<<NADJ, 128>>>();
    scanC_kernel<<<dim3(NT, NADJ), 1024>>>();
    scatter_kernel<<<EDGE8_BLOCKS, 256>>>(adj_rows, adj_cols, adj_vals);

    // ---- composed weights + fused s0 (both metas) ----
    wcomb_kernel<<<6, 256>>>(cell_aff_W, cell_aff_b, ws_W, ws_b);
    s0_kernel<<<dim3(S0_BLOCKS, 3), 256>>>(feats0, feats1, feats2);

    // ---- state chain, both metas per launch ----
    spmm_gather_kernel<1><<<dim3(GATH_BLOCKS, 2), 256>>>(idxes_seq, idxes_res);
    spmm_gather_kernel<2><<<dim3(GATH_BLOCKS, 2), 256>>>(idxes_seq, idxes_res);
    spmm_gather_kernel<3><<<dim3(GATH_BLOCKS, 2), 256>>>(idxes_seq, idxes_res);

    // ---- post (both metas) + mix ----
    post_kernel<<<dim3(POST_BLOCKS, 2), 256>>>(cell_norm_g, cell_norm_b,
                                               attn1_W, attn1_b, attn2_W, attn2_b);
    mix_kernel<<<MIX_BLOCKS, 256>>>(out);
}